// round 12
// baseline (speedup 1.0000x reference)
#include <cuda_runtime.h>
#include <cuda_bf16.h>

// SGNS: out[b] = [1-s, s], s = sigmoid( sum_w (W1[w,i1]+b1[w]) * (W2[w,i2]+b2[w]) )
// W1, W2: [128, 100000] row-major f32. idx1, idx2: [4096] int32.
//
// FINAL — converged at the hardware floor: 10.72-10.75us (three identical
// sources measured within one 32ns timer tick). One warp per TWO batch
// elements: 16 independent gather LDGs issued back-to-back (MLP=16/warp).
// Bias loads shared across both elements. float2 stores. 256-thread CTAs.
//
// Floor evidence (session matrix): LDG, TMA box(8,128) gather, and
// L2-evict_last-policy variants all measure identically; occupancy 19-39%,
// MLP 8/16, and block shape are all neutral; concurrent LDG+TMA front-end
// mixing regresses 2.2x; per-launch transpose-to-scratch costs ~200MB/launch
// and is strictly worse. The ~1M scattered 32B-sector requests per launch
// are an invariant of the stride-400KB random dual-gather; the shared
// L1tex-wavefront/L2 service path is the binding resource.

#define D_DIM 100000
#define W_DIM 128
#define BATCH 4096

__global__ __launch_bounds__(256) void sgns_kernel(
    const int* __restrict__ idx1,
    const int* __restrict__ idx2,
    const float* __restrict__ W1,
    const float* __restrict__ b1,
    const float* __restrict__ W2,
    const float* __restrict__ b2,
    float2* __restrict__ out)
{
    const unsigned warp = (blockIdx.x * blockDim.x + threadIdx.x) >> 5;
    const unsigned lane = threadIdx.x & 31;
    const unsigned b0 = warp * 2u;        // elements b0, b0+1

    // Broadcast index loads (one sector each).
    const long long i1a = idx1[b0],     i2a = idx2[b0];
    const long long i1b = idx1[b0 + 1], i2b = idx2[b0 + 1];

    const long long row = (long long)lane * D_DIM;

    // 16 independent gathers, issued back-to-back.
    const float* q1a = W1 + row + i1a;
    const float* q2a = W2 + row + i2a;
    const float* q1b = W1 + row + i1b;
    const float* q2b = W2 + row + i2b;

    const float a0 = __ldg(q1a + 0LL * 32 * D_DIM);
    const float a1 = __ldg(q1a + 1LL * 32 * D_DIM);
    const float a2 = __ldg(q1a + 2LL * 32 * D_DIM);
    const float a3 = __ldg(q1a + 3LL * 32 * D_DIM);
    const float c0 = __ldg(q2a + 0LL * 32 * D_DIM);
    const float c1 = __ldg(q2a + 1LL * 32 * D_DIM);
    const float c2 = __ldg(q2a + 2LL * 32 * D_DIM);
    const float c3 = __ldg(q2a + 3LL * 32 * D_DIM);

    const float g0 = __ldg(q1b + 0LL * 32 * D_DIM);
    const float g1 = __ldg(q1b + 1LL * 32 * D_DIM);
    const float g2 = __ldg(q1b + 2LL * 32 * D_DIM);
    const float g3 = __ldg(q1b + 3LL * 32 * D_DIM);
    const float h0 = __ldg(q2b + 0LL * 32 * D_DIM);
    const float h1 = __ldg(q2b + 1LL * 32 * D_DIM);
    const float h2 = __ldg(q2b + 2LL * 32 * D_DIM);
    const float h3 = __ldg(q2b + 3LL * 32 * D_DIM);

    // Bias loads shared by both elements.
    const float e0 = b1[lane +  0], e1 = b1[lane + 32],
                e2 = b1[lane + 64], e3 = b1[lane + 96];
    const float f0 = b2[lane +  0], f1 = b2[lane + 32],
                f2 = b2[lane + 64], f3 = b2[lane + 96];

    float accA = (a0 + e0) * (c0 + f0)
               + (a1 + e1) * (c1 + f1)
               + (a2 + e2) * (c2 + f2)
               + (a3 + e3) * (c3 + f3);

    float accB = (g0 + e0) * (h0 + f0)
               + (g1 + e1) * (h1 + f1)
               + (g2 + e2) * (h2 + f2)
               + (g3 + e3) * (h3 + f3);

    #pragma unroll
    for (int off = 16; off > 0; off >>= 1) {
        accA += __shfl_xor_sync(0xFFFFFFFFu, accA, off);
        accB += __shfl_xor_sync(0xFFFFFFFFu, accB, off);
    }

    if (lane == 0) {
        const float sA = 1.0f / (1.0f + expf(-accA));
        const float sB = 1.0f / (1.0f + expf(-accB));
        out[b0 + 0] = make_float2(1.0f - sA, sA);
        out[b0 + 1] = make_float2(1.0f - sB, sB);
    }
}

extern "C" void kernel_launch(void* const* d_in, const int* in_sizes, int n_in,
                              void* d_out, int out_size)
{
    const int*   idx1 = (const int*)  d_in[0];
    const int*   idx2 = (const int*)  d_in[1];
    const float* W1   = (const float*)d_in[2];
    const float* b1   = (const float*)d_in[3];
    const float* W2   = (const float*)d_in[4];
    const float* b2   = (const float*)d_in[5];
    float2* out = (float2*)d_out;

    // 2048 warps (2 elements each) = 256 CTAs x 256 threads.
    sgns_kernel<<<BATCH / 16, 256>>>(idx1, idx2, W1, b1, W2, b2, out);
}

// round 13
// speedup vs baseline: 1.0239x; 1.0239x over previous
#include <cuda_runtime.h>
#include <cuda_bf16.h>

// SGNS: out[b] = [1-s, s], s = sigmoid( sum_w (W1[w,i1]+b1[w]) * (W2[w,i2]+b2[w]) )
// W1, W2: [128, 100000] row-major f32. idx1, idx2: [4096] int32.
//
// FINAL — converged at the hardware floor: 10.72-10.98us across four runs of
// identical source (run-to-run noise ~±2.5%). One warp per TWO batch
// elements: 16 independent gather LDGs issued back-to-back (MLP=16/warp).
// Bias loads shared across both elements. float2 stores. 256-thread CTAs.
//
// Floor evidence (session matrix): LDG, TMA box(8,128) gather, and
// L2-evict_last-policy variants all measure identically; occupancy 19-39%,
// MLP 8/16, and block shape are all neutral; concurrent LDG+TMA front-end
// mixing regresses 2.2x; per-launch transpose-to-scratch costs ~200MB/launch
// and is strictly worse. The ~1M scattered 32B-sector requests per launch
// are an invariant of the stride-400KB random dual-gather; the shared
// L1tex-wavefront/L2 service path is the binding resource.

#define D_DIM 100000
#define W_DIM 128
#define BATCH 4096

__global__ __launch_bounds__(256) void sgns_kernel(
    const int* __restrict__ idx1,
    const int* __restrict__ idx2,
    const float* __restrict__ W1,
    const float* __restrict__ b1,
    const float* __restrict__ W2,
    const float* __restrict__ b2,
    float2* __restrict__ out)
{
    const unsigned warp = (blockIdx.x * blockDim.x + threadIdx.x) >> 5;
    const unsigned lane = threadIdx.x & 31;
    const unsigned b0 = warp * 2u;        // elements b0, b0+1

    // Broadcast index loads (one sector each).
    const long long i1a = idx1[b0],     i2a = idx2[b0];
    const long long i1b = idx1[b0 + 1], i2b = idx2[b0 + 1];

    const long long row = (long long)lane * D_DIM;

    // 16 independent gathers, issued back-to-back.
    const float* q1a = W1 + row + i1a;
    const float* q2a = W2 + row + i2a;
    const float* q1b = W1 + row + i1b;
    const float* q2b = W2 + row + i2b;

    const float a0 = __ldg(q1a + 0LL * 32 * D_DIM);
    const float a1 = __ldg(q1a + 1LL * 32 * D_DIM);
    const float a2 = __ldg(q1a + 2LL * 32 * D_DIM);
    const float a3 = __ldg(q1a + 3LL * 32 * D_DIM);
    const float c0 = __ldg(q2a + 0LL * 32 * D_DIM);
    const float c1 = __ldg(q2a + 1LL * 32 * D_DIM);
    const float c2 = __ldg(q2a + 2LL * 32 * D_DIM);
    const float c3 = __ldg(q2a + 3LL * 32 * D_DIM);

    const float g0 = __ldg(q1b + 0LL * 32 * D_DIM);
    const float g1 = __ldg(q1b + 1LL * 32 * D_DIM);
    const float g2 = __ldg(q1b + 2LL * 32 * D_DIM);
    const float g3 = __ldg(q1b + 3LL * 32 * D_DIM);
    const float h0 = __ldg(q2b + 0LL * 32 * D_DIM);
    const float h1 = __ldg(q2b + 1LL * 32 * D_DIM);
    const float h2 = __ldg(q2b + 2LL * 32 * D_DIM);
    const float h3 = __ldg(q2b + 3LL * 32 * D_DIM);

    // Bias loads shared by both elements.
    const float e0 = b1[lane +  0], e1 = b1[lane + 32],
                e2 = b1[lane + 64], e3 = b1[lane + 96];
    const float f0 = b2[lane +  0], f1 = b2[lane + 32],
                f2 = b2[lane + 64], f3 = b2[lane + 96];

    float accA = (a0 + e0) * (c0 + f0)
               + (a1 + e1) * (c1 + f1)
               + (a2 + e2) * (c2 + f2)
               + (a3 + e3) * (c3 + f3);

    float accB = (g0 + e0) * (h0 + f0)
               + (g1 + e1) * (h1 + f1)
               + (g2 + e2) * (h2 + f2)
               + (g3 + e3) * (h3 + f3);

    #pragma unroll
    for (int off = 16; off > 0; off >>= 1) {
        accA += __shfl_xor_sync(0xFFFFFFFFu, accA, off);
        accB += __shfl_xor_sync(0xFFFFFFFFu, accB, off);
    }

    if (lane == 0) {
        const float sA = 1.0f / (1.0f + expf(-accA));
        const float sB = 1.0f / (1.0f + expf(-accB));
        out[b0 + 0] = make_float2(1.0f - sA, sA);
        out[b0 + 1] = make_float2(1.0f - sB, sB);
    }
}

extern "C" void kernel_launch(void* const* d_in, const int* in_sizes, int n_in,
                              void* d_out, int out_size)
{
    const int*   idx1 = (const int*)  d_in[0];
    const int*   idx2 = (const int*)  d_in[1];
    const float* W1   = (const float*)d_in[2];
    const float* b1   = (const float*)d_in[3];
    const float* W2   = (const float*)d_in[4];
    const float* b2   = (const float*)d_in[5];
    float2* out = (float2*)d_out;

    // 2048 warps (2 elements each) = 256 CTAs x 256 threads.
    sgns_kernel<<<BATCH / 16, 256>>>(idx1, idx2, W1, b1, W2, b2, out);
}